// round 17
// baseline (speedup 1.0000x reference)
#include <cuda_runtime.h>

// ---------------------------------------------------------------------------
// Bit-exact fused SNN kernel, v15: single-barrier software-pipelined step.
// Phase(t) = { FC(t-2) on warp0 || stage2(t-1) all warps || stage1(t) warps
// 1-7 || x-load(t+1) warps 1-7 } with ONE __syncthreads per phase and NO
// named barrier (x(t+1) is consumed only after the next full barrier).
// Double-buffered x / spk1 / spk2; W3 moved to global (L2-hot, read by FC
// on warp0 off the critical path). All FMA blocks byte-identical to R12
// (best verified kernel): pure code motion + buffer parity.
// PROTECTED arithmetic (rel_err == 0.0 invariant):
//   conv: per-output sequential FMA in (ky, kx, ic) order
//   FC:   sequential FMA q = 0..799
//   LIF:  m' = fsub(fma(0.95, m, cur), reset)
//   pool-then-bias
// FFMA2 = two INDEPENDENT IEEE fma.rn; pairing never mixes chains.
// ---------------------------------------------------------------------------

#define T_STEPS 100
#define BATCH   256

typedef unsigned long long u64;

// smem layout (float offsets)
constexpr int OFF_W1  = 0;       // w1 cl [oc][ky][kx][ic2]          = 600
constexpr int OFF_B1  = 600;     // 12 (+4 pad)
constexpr int OFF_W1P = 616;     // paired w1 [oc][ry-1][kx][4]      = 960
constexpr int OFF_W2  = 1576;    // w2 cl [32][25][12]               = 9600
constexpr int OFF_B2  = 11176;   // 32
constexpr int OFF_B3  = 11208;   // 12
constexpr int OFF_X   = 11220;   // x cl [2 sets][32 rows][66]       = 4224
constexpr int OFF_S1  = 15444;   // spk1 [2 sets][A 2352 + B 2016]   = 8736
constexpr int OFF_S2  = 24180;   // spk2 [2 sets][800]               = 1600
constexpr int SMEM_FLOATS = 25780;
constexpr int SMEM_BYTES  = SMEM_FLOATS * 4;

constexpr int XSET  = 2112;      // x set stride
constexpr int S1SET = 4368;      // spk1 set stride (A 2352 + B 2016)
constexpr int S1BO  = 2352;      // B offset within a set

__device__ __forceinline__ u64 pack2(float lo, float hi) {
    u64 r;
    asm("mov.b64 %0, {%1, %2};" : "=l"(r) : "f"(lo), "f"(hi));
    return r;
}
__device__ __forceinline__ void unpack2(float& lo, float& hi, u64 v) {
    asm("mov.b64 {%0, %1}, %2;" : "=f"(lo), "=f"(hi) : "l"(v));
}
// d.lo = fma.rn(a.lo, b.lo, d.lo); d.hi = fma.rn(a.hi, b.hi, d.hi)
__device__ __forceinline__ void ffma2(u64& d, u64 a, u64 b) {
    asm("fma.rn.f32x2 %0, %1, %2, %0;" : "+l"(d) : "l"(a), "l"(b));
}

__device__ __forceinline__ float lif_step(float& mem, float cur) {
    float reset = (mem > 1.0f) ? 1.0f : 0.0f;
    float mn = __fsub_rn(__fmaf_rn(0.95f, mem, cur), reset);
    mem = mn;
    return (mn > 1.0f) ? 1.0f : 0.0f;
}

// FC row k for step tt: W3 row from GLOBAL (L2-hot), spk2 from smem set par.
// Chain: strict sequential q = 0..799 (float4 blocks, ascending) — unchanged.
__device__ __forceinline__ void fc_stage(const float* __restrict__ s,
                                         const float* __restrict__ W3,
                                         float& mem3, int tt, int b, int k,
                                         float* __restrict__ out) {
    const float4* wr = reinterpret_cast<const float4*>(W3 + k * 800);
    const float4* xv = reinterpret_cast<const float4*>(
        s + OFF_S2 + (tt & 1) * 800);
    float acc = 0.f;
    #pragma unroll 8
    for (int q = 0; q < 200; q++) {
        float4 w = wr[q], x = xv[q];
        acc = fmaf(x.x, w.x, acc);
        acc = fmaf(x.y, w.y, acc);
        acc = fmaf(x.z, w.z, acc);
        acc = fmaf(x.w, w.w, acc);
    }
    float cur = __fadd_rn(acc, s[OFF_B3 + k]);
    out[((long long)tt * BATCH + b) * 10 + k] = lif_step(mem3, cur);
}

__global__ void __launch_bounds__(256, 2) snn_kernel(
    const float* __restrict__ x,
    const float* __restrict__ W1, const float* __restrict__ b1,
    const float* __restrict__ W2, const float* __restrict__ b2,
    const float* __restrict__ W3, const float* __restrict__ b3,
    float* __restrict__ out)
{
    extern __shared__ float s[];
    const int b    = blockIdx.x;
    const int tid  = threadIdx.x;
    const int lane = tid & 31;
    const int w    = tid >> 5;

    // --- weights -> smem ---
    for (int i = tid; i < 600; i += 256) {
        int oc = i / 50, r = i % 50, ic = r / 25, k = r % 25;
        s[OFF_W1 + (oc * 25 + k) * 2 + ic] = W1[i];
    }
    // paired conv1 weights: [oc][ry-1][kx][{(ry,ic0),(ry-1,ic0),(ry,ic1),(ry-1,ic1)}]
    for (int i = tid; i < 960; i += 256) {
        int q = i & 3, idx = i >> 2;
        int kx = idx % 5, ryp = (idx / 5) % 4, oc = idx / 20;
        int ry = ryp + 1;
        int ic = q >> 1;
        int useKy = (q & 1) ? (ry - 1) : ry;
        s[OFF_W1P + i] = W1[oc * 50 + ic * 25 + useKy * 5 + kx];
    }
    for (int i = tid; i < 9600; i += 256) {
        int oc = i / 300, r = i % 300, ic = r / 25, k = r % 25;
        s[OFF_W2 + oc * 300 + k * 12 + ic] = W2[i];
    }
    for (int i = tid; i < 12; i += 256) s[OFF_B1 + i] = b1[i];
    for (int i = tid; i < 32; i += 256) s[OFF_B2 + i] = b2[i];
    for (int i = tid; i < 12; i += 256) s[OFF_B3 + i] = (i < 10) ? b3[i] : 0.f;

    // preload x(t=0) into x set 0 (all 256 threads, scalar scatter)
    {
        const float* xg = x + (long long)b * 2048;
        for (int idx = tid; idx < 2048; idx += 256) {
            int ic = idx >> 10, pos = idx & 1023;
            int r = pos >> 5, c = pos & 31;
            s[OFF_X + r * 66 + c * 2 + ic] = xg[idx];
        }
    }
    __syncthreads();

    float mem1r[12];
    #pragma unroll
    for (int k = 0; k < 12; k++) mem1r[k] = 0.f;
    float mem2r[4];
    #pragma unroll
    for (int k = 0; k < 4; k++) mem2r[k] = 0.f;
    float mem3r = 0.f;

    // stage2 positions: m<3 -> p = 8m + w; m=3 -> p=24, warp 7 only (R12)
    const bool has4 = (w == 7);
    int pim[4], pjm[4];
    #pragma unroll
    for (int m = 0; m < 4; m++) {
        int p = (m < 3) ? (8 * m + w) : 24;
        pim[m] = p / 5;
        pjm[m] = p % 5;
    }

    // ===================== single-barrier pipelined loop ===================
    // phase t: FC(t-2) | stage2(t-1) | stage1(t) | xload(t+1), one barrier.
    for (int t = 0; t < T_STEPS + 2; t++) {
        // ---------------- stage2(t-1): all warps --------------------------
        if (t >= 1 && t <= T_STEPS) {
            const int pS = (t - 1) & 1;
            const float* s1a = s + OFF_S1 + pS * S1SET;
            const float* s1b = s1a + S1BO;
            float* s2o = s + OFF_S2 + pS * 800;
            const float* wocb = s + OFF_W2 + lane * 300;
            u64 A0[4], A1[4];
            #pragma unroll
            for (int m = 0; m < 4; m++) { A0[m] = 0ULL; A1[m] = 0ULL; }

            for (int ky = 0; ky < 5; ky++) {
                const float* pb[4];
                int cs4[4];
                #pragma unroll
                for (int m = 0; m < 4; m++) {
                    int ra = 2 * pim[m] + ky;
                    if (ra & 1) {
                        cs4[m] = 144;
                        pb[m] = s1b + ((ra - 1) >> 1) * 24 + 2 * pjm[m] * 144;
                    } else {
                        cs4[m] = 168;
                        pb[m] = s1a + (ra >> 1) * 24 + 2 * pjm[m] * 168;
                    }
                }
                u64 wcur[12], wprev[12];
                #pragma unroll
                for (int j = 0; j < 12; j++) { wcur[j] = 0ULL; wprev[j] = 0ULL; }
                #pragma unroll
                for (int c = 0; c < 6; c++) {
                    #pragma unroll
                    for (int j = 0; j < 12; j++) wprev[j] = wcur[j];
                    if (c < 5) {
                        const float4* wv4 = reinterpret_cast<const float4*>(
                            wocb + (ky * 5 + c) * 12);
                        float4 w0 = wv4[0], w1 = wv4[1], w2 = wv4[2];
                        wcur[0]  = pack2(w0.x, w0.x); wcur[1]  = pack2(w0.y, w0.y);
                        wcur[2]  = pack2(w0.z, w0.z); wcur[3]  = pack2(w0.w, w0.w);
                        wcur[4]  = pack2(w1.x, w1.x); wcur[5]  = pack2(w1.y, w1.y);
                        wcur[6]  = pack2(w1.z, w1.z); wcur[7]  = pack2(w1.w, w1.w);
                        wcur[8]  = pack2(w2.x, w2.x); wcur[9]  = pack2(w2.y, w2.y);
                        wcur[10] = pack2(w2.z, w2.z); wcur[11] = pack2(w2.w, w2.w);
                    }
                    #pragma unroll
                    for (int m = 0; m < 4; m++) {
                        if (m < 3 || has4) {
                            const ulonglong2* xc =
                                reinterpret_cast<const ulonglong2*>(
                                    pb[m] + c * cs4[m]);
                            ulonglong2 x0 = xc[0], x1 = xc[1], x2 = xc[2];
                            ulonglong2 x3 = xc[3], x4 = xc[4], x5 = xc[5];
                            if (c < 5) {
                                ffma2(A0[m], wcur[0],  x0.x);
                                ffma2(A0[m], wcur[1],  x0.y);
                                ffma2(A0[m], wcur[2],  x1.x);
                                ffma2(A0[m], wcur[3],  x1.y);
                                ffma2(A0[m], wcur[4],  x2.x);
                                ffma2(A0[m], wcur[5],  x2.y);
                                ffma2(A0[m], wcur[6],  x3.x);
                                ffma2(A0[m], wcur[7],  x3.y);
                                ffma2(A0[m], wcur[8],  x4.x);
                                ffma2(A0[m], wcur[9],  x4.y);
                                ffma2(A0[m], wcur[10], x5.x);
                                ffma2(A0[m], wcur[11], x5.y);
                            }
                            if (c >= 1) {
                                ffma2(A1[m], wprev[0],  x0.x);
                                ffma2(A1[m], wprev[1],  x0.y);
                                ffma2(A1[m], wprev[2],  x1.x);
                                ffma2(A1[m], wprev[3],  x1.y);
                                ffma2(A1[m], wprev[4],  x2.x);
                                ffma2(A1[m], wprev[5],  x2.y);
                                ffma2(A1[m], wprev[6],  x3.x);
                                ffma2(A1[m], wprev[7],  x3.y);
                                ffma2(A1[m], wprev[8],  x4.x);
                                ffma2(A1[m], wprev[9],  x4.y);
                                ffma2(A1[m], wprev[10], x5.x);
                                ffma2(A1[m], wprev[11], x5.y);
                            }
                        }
                    }
                }
            }
            #pragma unroll
            for (int m = 0; m < 4; m++) {
                if (m < 3 || has4) {
                    int p = (m < 3) ? (8 * m + w) : 24;
                    float a00, a10, a01, a11;
                    unpack2(a00, a10, A0[m]);
                    unpack2(a01, a11, A1[m]);
                    float pm = fmaxf(fmaxf(a00, a01), fmaxf(a10, a11));
                    float cur = __fadd_rn(pm, s[OFF_B2 + lane]);
                    s2o[lane * 25 + p] = lif_step(mem2r[m], cur);
                }
            }
        }

        // ---------------- FC(t-2) on warp0 | stage1(t)+xload on warps 1-7 --
        if (w == 0) {
            if (t >= 2 && lane < 10)
                fc_stage(s, W3, mem3r, t - 2, b, lane, out);
        } else {
            if (t < T_STEPS && tid < 228) {
                const float* xs = s + OFF_X + (t & 1) * XSET;
                float* s1ao = s + OFF_S1 + (t & 1) * S1SET;
                float* s1bo = s1ao + S1BO;
                // ocg by thread-half (warp-uniform ocb -> broadcast weights)
                const int task = tid - 32;
                const int ocg = (task < 98) ? 0 : 1;
                const int pos = (task < 98) ? task : (task - 98);
                const int i1 = pos / 7, jp = pos % 7;
                const int cb = 4 * jp;
                const int ocb = ocg * 6;

                // --- ry = 0: scalar, side0 (conv row 2i1, ky=0) ---
                float a0s[24];
                #pragma unroll
                for (int k = 0; k < 24; k++) a0s[k] = 0.f;
                {
                    const float2* xr = reinterpret_cast<const float2*>(
                        xs + (2 * i1) * 66 + cb * 2);
                    float2 win[8];
                    #pragma unroll
                    for (int c = 0; c < 8; c++) win[c] = xr[c];
                    #pragma unroll
                    for (int kx = 0; kx < 5; kx++)
                        #pragma unroll
                        for (int oc = 0; oc < 6; oc++) {
                            float2 wv = *reinterpret_cast<const float2*>(
                                s + OFF_W1 + ((ocb + oc) * 25 + kx) * 2);
                            #pragma unroll
                            for (int c = 0; c < 4; c++) {
                                float a = a0s[oc * 4 + c];
                                a = fmaf(wv.x, win[kx + c].x, a);
                                a = fmaf(wv.y, win[kx + c].y, a);
                                a0s[oc * 4 + c] = a;
                            }
                        }
                }
                u64 P[24];
                #pragma unroll
                for (int k = 0; k < 24; k++) P[k] = pack2(a0s[k], 0.f);

                // --- ry = 1..4: paired (side0 ky=ry, side1 ky=ry-1) ---
                #pragma unroll
                for (int ry = 1; ry <= 4; ry++) {
                    const float2* xr = reinterpret_cast<const float2*>(
                        xs + (2 * i1 + ry) * 66 + cb * 2);
                    float2 win[8];
                    #pragma unroll
                    for (int c = 0; c < 8; c++) win[c] = xr[c];
                    u64 xd[16];
                    #pragma unroll
                    for (int j = 0; j < 8; j++) {
                        xd[2 * j]     = pack2(win[j].x, win[j].x);
                        xd[2 * j + 1] = pack2(win[j].y, win[j].y);
                    }
                    #pragma unroll
                    for (int kx = 0; kx < 5; kx++)
                        #pragma unroll
                        for (int oc = 0; oc < 6; oc++) {
                            ulonglong2 wq = *reinterpret_cast<const ulonglong2*>(
                                s + OFF_W1P +
                                (((ocb + oc) * 4 + (ry - 1)) * 5 + kx) * 4);
                            #pragma unroll
                            for (int c = 0; c < 4; c++) {
                                ffma2(P[oc * 4 + c], wq.x, xd[2 * (kx + c)]);
                                ffma2(P[oc * 4 + c], wq.y, xd[2 * (kx + c) + 1]);
                            }
                        }
                }
                float a1s[24];
                #pragma unroll
                for (int k = 0; k < 24; k++) unpack2(a0s[k], a1s[k], P[k]);

                // --- ry = 5: scalar, side1 (conv row 2i1+1, ky=4) ---
                {
                    const float2* xr = reinterpret_cast<const float2*>(
                        xs + (2 * i1 + 5) * 66 + cb * 2);
                    float2 win[8];
                    #pragma unroll
                    for (int c = 0; c < 8; c++) win[c] = xr[c];
                    #pragma unroll
                    for (int kx = 0; kx < 5; kx++)
                        #pragma unroll
                        for (int oc = 0; oc < 6; oc++) {
                            float2 wv = *reinterpret_cast<const float2*>(
                                s + OFF_W1 + ((ocb + oc) * 25 + 20 + kx) * 2);
                            #pragma unroll
                            for (int c = 0; c < 4; c++) {
                                float a = a1s[oc * 4 + c];
                                a = fmaf(wv.x, win[kx + c].x, a);
                                a = fmaf(wv.y, win[kx + c].y, a);
                                a1s[oc * 4 + c] = a;
                            }
                        }
                }

                // pool + LIF + dual-layout spike stores
                #pragma unroll
                for (int oc = 0; oc < 6; oc++) {
                    float p0 = fmaxf(fmaxf(a0s[oc*4+0], a0s[oc*4+1]),
                                     fmaxf(a1s[oc*4+0], a1s[oc*4+1]));
                    float p1 = fmaxf(fmaxf(a0s[oc*4+2], a0s[oc*4+3]),
                                     fmaxf(a1s[oc*4+2], a1s[oc*4+3]));
                    float bias = s[OFF_B1 + ocb + oc];
                    float sp0 = lif_step(mem1r[oc * 2 + 0], __fadd_rn(p0, bias));
                    float sp1 = lif_step(mem1r[oc * 2 + 1], __fadd_rn(p1, bias));
                    const int r = i1, ch = ocb + oc;
                    const int rpA = r >> 1, qA = r & 1;
                    const int c0 = 2 * jp, c1 = 2 * jp + 1;
                    s1ao[((c0 * 7 + rpA) * 12 + ch) * 2 + qA] = sp0;
                    s1ao[((c1 * 7 + rpA) * 12 + ch) * 2 + qA] = sp1;
                    if (r >= 1 && r <= 12) {
                        const int rpB = (r - 1) >> 1, qB = 1 - (r & 1);
                        s1bo[((c0 * 6 + rpB) * 12 + ch) * 2 + qB] = sp0;
                        s1bo[((c1 * 6 + rpB) * 12 + ch) * 2 + qB] = sp1;
                    }
                }
            }
            // ---- x(t+1) load (consumed only after the barrier below) ----
            if (t + 1 < T_STEPS) {
                const float* xg = x + ((long long)(t + 1) * BATCH + b) * 2048;
                float* xw = s + OFF_X + ((t + 1) & 1) * XSET;
                for (int idx = tid - 32; idx < 2048; idx += 224) {
                    int ic = idx >> 10, pos = idx & 1023;
                    int r = pos >> 5, c = pos & 31;
                    xw[r * 66 + c * 2 + ic] = xg[idx];
                }
            }
        }
        __syncthreads();
    }
}

extern "C" void kernel_launch(void* const* d_in, const int* in_sizes, int n_in,
                              void* d_out, int out_size) {
    const float* x  = (const float*)d_in[0];
    const float* W1 = (const float*)d_in[1];
    const float* b1 = (const float*)d_in[2];
    const float* W2 = (const float*)d_in[3];
    const float* b2 = (const float*)d_in[4];
    const float* W3 = (const float*)d_in[5];
    const float* b3 = (const float*)d_in[6];
    float* out = (float*)d_out;

    cudaFuncSetAttribute(snn_kernel,
                         cudaFuncAttributeMaxDynamicSharedMemorySize,
                         SMEM_BYTES);
    snn_kernel<<<BATCH, 256, SMEM_BYTES>>>(x, W1, b1, W2, b2, W3, b3, out);
}